// round 16
// baseline (speedup 1.0000x reference)
#include <cuda_runtime.h>

// u: [16384, 2, 2048] float32 -> out: [16384, 2, 2048] float32
// du = 6th-order central diff along l (interior [10, 2038)), zero in ghosts.
// out[:,0,:] = -(u1*du0 + u0*du1)
// out[:,1,:] = -(2*du0 + u1*du1)
//
// R16: R15 shuffle-halo kernel (best: 80.35us, 6481 GB/s) with
//  (1) ALL loads front-batched (main 4 LDG.128 + predicated edge patches)
//  (2) __launch_bounds__(256, 6) to cap regs and lift occupancy ~50->60%.

#define L 2048
#define IGST 10
#define ROW 4096   // 2 channels * L

__global__ __launch_bounds__(256, 6) void centdif_kernel(const float* __restrict__ u,
                                                         float* __restrict__ out) {
    const int tid = threadIdx.x;
    const int lane = tid & 31;
    const long base = (long)blockIdx.x * ROW;
    const float4* __restrict__ up = (const float4*)(u + base);
    float4* __restrict__ op = (float4*)(out + base);

    // ---- Front-batched loads: mains first, then edge patches (all independent) ----
    float4 B0[2], B1[2];
#pragma unroll
    for (int i = 0; i < 2; i++) {
        const int ck = tid + i * 256;
        B0[i] = up[ck];
        B1[i] = up[512 + ck];
    }

    float4 A0e[2], A1e[2], C0e[2], C1e[2];
#pragma unroll
    for (int i = 0; i < 2; i++) {
        const int ck = tid + i * 256;
        const int ckm = ck > 0 ? ck - 1 : 0;      // clamped: those outputs are ghost
        const int ckp = ck < 511 ? ck + 1 : 511;
        if (lane == 0)  { A0e[i] = up[ckm]; A1e[i] = up[512 + ckm]; }
        if (lane == 31) { C0e[i] = up[ckp]; C1e[i] = up[512 + ckp]; }
    }

    const float c = 1.0f / (60.0f * 0.012f);

#pragma unroll
    for (int i = 0; i < 2; i++) {
        const int ck = tid + i * 256;   // chunk 0..511 -> outputs l = 4*ck..4*ck+3
        const int l0 = 4 * ck;

        // Halo exchange, channel 0
        float a0y = __shfl_up_sync(0xffffffffu, B0[i].y, 1);
        float a0z = __shfl_up_sync(0xffffffffu, B0[i].z, 1);
        float a0w = __shfl_up_sync(0xffffffffu, B0[i].w, 1);
        float c0x = __shfl_down_sync(0xffffffffu, B0[i].x, 1);
        float c0y = __shfl_down_sync(0xffffffffu, B0[i].y, 1);
        float c0z = __shfl_down_sync(0xffffffffu, B0[i].z, 1);
        if (lane == 0)  { a0y = A0e[i].y; a0z = A0e[i].z; a0w = A0e[i].w; }
        if (lane == 31) { c0x = C0e[i].x; c0y = C0e[i].y; c0z = C0e[i].z; }

        // Halo exchange, channel 1
        float a1y = __shfl_up_sync(0xffffffffu, B1[i].y, 1);
        float a1z = __shfl_up_sync(0xffffffffu, B1[i].z, 1);
        float a1w = __shfl_up_sync(0xffffffffu, B1[i].w, 1);
        float c1x = __shfl_down_sync(0xffffffffu, B1[i].x, 1);
        float c1y = __shfl_down_sync(0xffffffffu, B1[i].y, 1);
        float c1z = __shfl_down_sync(0xffffffffu, B1[i].z, 1);
        if (lane == 0)  { a1y = A1e[i].y; a1z = A1e[i].z; a1w = A1e[i].w; }
        if (lane == 31) { c1x = C1e[i].x; c1y = C1e[i].y; c1z = C1e[i].z; }

        // wv[j] = u[l0-3+j]; output k uses taps wv[k..k+6], center wv[k+3]
        const float w0v[10] = {a0y, a0z, a0w, B0[i].x, B0[i].y, B0[i].z, B0[i].w, c0x, c0y, c0z};
        const float w1v[10] = {a1y, a1z, a1w, B1[i].x, B1[i].y, B1[i].z, B1[i].w, c1x, c1y, c1z};

        float o0[4], o1[4];
#pragma unroll
        for (int k = 0; k < 4; k++) {
            const int p = l0 + k;
            const bool in = (p >= IGST) && (p < L - IGST);
            float du0 = (-w0v[k] + 9.0f * w0v[k + 1] - 45.0f * w0v[k + 2]
                         + 45.0f * w0v[k + 4] - 9.0f * w0v[k + 5] + w0v[k + 6]) * c;
            float du1 = (-w1v[k] + 9.0f * w1v[k + 1] - 45.0f * w1v[k + 2]
                         + 45.0f * w1v[k + 4] - 9.0f * w1v[k + 5] + w1v[k + 6]) * c;
            du0 = in ? du0 : 0.0f;
            du1 = in ? du1 : 0.0f;
            const float u0 = w0v[k + 3];
            const float u1 = w1v[k + 3];
            o0[k] = -(u1 * du0 + u0 * du1);
            o1[k] = -(2.0f * du0 + u1 * du1);
        }

        op[ck]       = make_float4(o0[0], o0[1], o0[2], o0[3]);
        op[512 + ck] = make_float4(o1[0], o1[1], o1[2], o1[3]);
    }
}

extern "C" void kernel_launch(void* const* d_in, const int* in_sizes, int n_in,
                              void* d_out, int out_size) {
    const float* u = (const float*)d_in[0];
    float* out = (float*)d_out;
    const int m = in_sizes[0] / ROW;  // 16384
    centdif_kernel<<<m, 256>>>(u, out);
}

// round 17
// speedup vs baseline: 1.0075x; 1.0075x over previous
#include <cuda_runtime.h>

// u: [16384, 2, 2048] float32 -> out: [16384, 2, 2048] float32
// du = 6th-order central diff along l (interior [10, 2038)), zero in ghosts.
// out[:,0,:] = -(u1*du0 + u0*du1)
// out[:,1,:] = -(2*du0 + u1*du1)
//
// FINAL — R15 warp-shuffle halo kernel. Session best: 80.35us bench,
// 74.2us kernel, 6481 GB/s (81% of spec; highest of 16 measured variants).
//   * no smem, no __syncthreads (removing the per-block barrier+round-trip
//     is what broke through the 6330 GB/s plateau of all smem variants)
//   * 256 thr/block, 4 front-batched LDG.128/thread (proven MLP point)
//   * stencil halo via __shfl_up/down; warp-edge lanes patch with
//     predicated LDG on already-resident lines (DRAM stays at 512MB floor)
//   * regs 48 / occ 50% — NOT occupancy-bound (R16 proved forcing occ up
//     via reg caps degrades scheduling and loses 2.3%)
// Ruled out by measurement: smem round-trip (6330 plateau), direct-global
// windows (dup wavefronts), cp.async fill/pipeline (drain bubbles),
// 512-thr / 128-thr shapes (MLP/warp-count), .cs hints (neutral),
// front-batched edge patches + launch_bounds(256,6) (regression).

#define L 2048
#define IGST 10
#define ROW 4096   // 2 channels * L

__global__ __launch_bounds__(256) void centdif_kernel(const float* __restrict__ u,
                                                      float* __restrict__ out) {
    const int tid = threadIdx.x;
    const int lane = tid & 31;
    const long base = (long)blockIdx.x * ROW;
    const float4* __restrict__ up = (const float4*)(u + base);
    float4* __restrict__ op = (float4*)(out + base);

    // Front-batched loads: 2 chunks x 2 channels = 4 LDG.128.
    float4 B0[2], B1[2];
#pragma unroll
    for (int i = 0; i < 2; i++) {
        const int ck = tid + i * 256;
        B0[i] = up[ck];
        B1[i] = up[512 + ck];
    }

    const float c = 1.0f / (60.0f * 0.012f);

#pragma unroll
    for (int i = 0; i < 2; i++) {
        const int ck = tid + i * 256;   // chunk 0..511 -> outputs l = 4*ck..4*ck+3
        const int l0 = 4 * ck;

        // Warp-edge patches (lane 0 needs chunk ck-1, lane 31 chunk ck+1).
        // Clamped at row ends; those outputs are ghost -> masked to 0 anyway.
        const int ckm = ck > 0 ? ck - 1 : 0;
        const int ckp = ck < 511 ? ck + 1 : 511;
        float4 A0e, A1e, C0e, C1e;
        if (lane == 0)  { A0e = up[ckm]; A1e = up[512 + ckm]; }
        if (lane == 31) { C0e = up[ckp]; C1e = up[512 + ckp]; }

        // Halo exchange, channel 0: left neighbor's .y.z.w, right neighbor's .x.y.z
        float a0y = __shfl_up_sync(0xffffffffu, B0[i].y, 1);
        float a0z = __shfl_up_sync(0xffffffffu, B0[i].z, 1);
        float a0w = __shfl_up_sync(0xffffffffu, B0[i].w, 1);
        float c0x = __shfl_down_sync(0xffffffffu, B0[i].x, 1);
        float c0y = __shfl_down_sync(0xffffffffu, B0[i].y, 1);
        float c0z = __shfl_down_sync(0xffffffffu, B0[i].z, 1);
        if (lane == 0)  { a0y = A0e.y; a0z = A0e.z; a0w = A0e.w; }
        if (lane == 31) { c0x = C0e.x; c0y = C0e.y; c0z = C0e.z; }

        // Halo exchange, channel 1
        float a1y = __shfl_up_sync(0xffffffffu, B1[i].y, 1);
        float a1z = __shfl_up_sync(0xffffffffu, B1[i].z, 1);
        float a1w = __shfl_up_sync(0xffffffffu, B1[i].w, 1);
        float c1x = __shfl_down_sync(0xffffffffu, B1[i].x, 1);
        float c1y = __shfl_down_sync(0xffffffffu, B1[i].y, 1);
        float c1z = __shfl_down_sync(0xffffffffu, B1[i].z, 1);
        if (lane == 0)  { a1y = A1e.y; a1z = A1e.z; a1w = A1e.w; }
        if (lane == 31) { c1x = C1e.x; c1y = C1e.y; c1z = C1e.z; }

        // wv[j] = u[l0-3+j]; output k uses taps wv[k..k+6], center wv[k+3]
        const float w0v[10] = {a0y, a0z, a0w, B0[i].x, B0[i].y, B0[i].z, B0[i].w, c0x, c0y, c0z};
        const float w1v[10] = {a1y, a1z, a1w, B1[i].x, B1[i].y, B1[i].z, B1[i].w, c1x, c1y, c1z};

        float o0[4], o1[4];
#pragma unroll
        for (int k = 0; k < 4; k++) {
            const int p = l0 + k;
            const bool in = (p >= IGST) && (p < L - IGST);
            float du0 = (-w0v[k] + 9.0f * w0v[k + 1] - 45.0f * w0v[k + 2]
                         + 45.0f * w0v[k + 4] - 9.0f * w0v[k + 5] + w0v[k + 6]) * c;
            float du1 = (-w1v[k] + 9.0f * w1v[k + 1] - 45.0f * w1v[k + 2]
                         + 45.0f * w1v[k + 4] - 9.0f * w1v[k + 5] + w1v[k + 6]) * c;
            du0 = in ? du0 : 0.0f;
            du1 = in ? du1 : 0.0f;
            const float u0 = w0v[k + 3];
            const float u1 = w1v[k + 3];
            o0[k] = -(u1 * du0 + u0 * du1);
            o1[k] = -(2.0f * du0 + u1 * du1);
        }

        op[ck]       = make_float4(o0[0], o0[1], o0[2], o0[3]);
        op[512 + ck] = make_float4(o1[0], o1[1], o1[2], o1[3]);
    }
}

extern "C" void kernel_launch(void* const* d_in, const int* in_sizes, int n_in,
                              void* d_out, int out_size) {
    const float* u = (const float*)d_in[0];
    float* out = (float*)d_out;
    const int m = in_sizes[0] / ROW;  // 16384
    centdif_kernel<<<m, 256>>>(u, out);
}